// round 4
// baseline (speedup 1.0000x reference)
#include <cuda_runtime.h>
#include <math.h>
#include <stdint.h>

// Problem constants
constexpr int kV = 50257;
constexpr int kH = 512;
constexpr int kS = 512;
constexpr int kB = 8;
constexpr int kT = 64;
constexpr int kM = kT * kB;          // 512 rows (t*B+b)
constexpr int NYB = 393;             // n-tiles of 128 -> 393*128 = 50304

// Scratch (device globals — allocation-free per harness rules)
__device__ float g_logits[(size_t)kM * kV];      // ~103 MB
__device__ float g_At2[kH * kM];                 // pre-tiled fragment-interleaved A (tf32)
__device__ float g_pmax[(size_t)NYB * kM];
__device__ float g_psum[(size_t)NYB * kM];
__device__ float g_prob[kM];
__device__ float g_rowmax[kM];
__device__ float g_rowsum[kM];
__device__ float g_zc[kM];
__device__ float g_q[kS * kB];
__device__ int   g_leader[kB * kS];

// ======================= helpers =======================
__device__ __forceinline__ float to_tf32(float x) {
    float r;
    asm("cvt.rna.tf32.f32 %0, %1;" : "=f"(r) : "f"(x));
    return r;
}
__device__ __forceinline__ uint32_t smem_u32(const void* p) {
    uint32_t a;
    asm("{ .reg .u64 t; cvta.to.shared.u64 t, %1; cvt.u32.u64 %0, t; }" : "=r"(a) : "l"(p));
    return a;
}
#define CP16(dst, src) \
    asm volatile("cp.async.cg.shared.global [%0], [%1], 16;" :: "r"(dst), "l"(src))
#define CP4(dst, src) \
    asm volatile("cp.async.ca.shared.global [%0], [%1], 4;" :: "r"(dst), "l"(src))
#define CPCOMMIT() asm volatile("cp.async.commit_group;" ::: "memory")
#define CPWAIT()   asm volatile("cp.async.wait_group 3;" ::: "memory")

__device__ __forceinline__ void mma_tf32(float* c, const float4& a, const float2& b) {
    asm volatile(
        "mma.sync.aligned.m16n8k8.row.col.f32.tf32.tf32.f32 "
        "{%0,%1,%2,%3}, {%4,%5,%6,%7}, {%8,%9}, {%0,%1,%2,%3};"
        : "+f"(c[0]), "+f"(c[1]), "+f"(c[2]), "+f"(c[3])
        : "r"(__float_as_uint(a.x)), "r"(__float_as_uint(a.y)),
          "r"(__float_as_uint(a.z)), "r"(__float_as_uint(a.w)),
          "r"(__float_as_uint(b.x)), "r"(__float_as_uint(b.y)));
}

// ======================= pre-pass: A -> pre-tiled fragment-interleaved (tf32) =======================
// Block layout (per mtile, ktile): 128(m) x 32(k) floats.
// off(kk,mm) = (((kg*8 + mm>>4)*8 + (mm&7))*4 + (kk&3))*4 + ((kk>>2)&1)*2 + ((mm>>3)&1)
__global__ void k_at(const float* __restrict__ A) {
    int idx = blockIdx.x * 256 + threadIdx.x;   // over kH*kM = 262144
    int m = idx >> 9, k = idx & 511;
    float v = to_tf32(A[(size_t)m * kH + k]);
    int mt = m >> 7, mm = m & 127;
    int ct = k >> 5, kk = k & 31;
    int kg = kk >> 3, l4 = kk & 3, hi = (kk >> 2) & 1;
    int off = (((kg * 8 + (mm >> 4)) * 8 + (mm & 7)) * 4 + l4) * 4 + hi * 2 + ((mm >> 3) & 1);
    g_At2[(size_t)(mt * 16 + ct) * 4096 + off] = v;
}

// ======================= GEMM: logits = A @ W + bias (mma.sync tf32) =======================
constexpr int BM = 128, BN = 128, KC = 32;
constexpr int NST = 4;
constexpr int NKT = kH / KC;              // 16 k-tiles
constexpr int STAGE_FLTS = 8192;          // A 4096 + B 4096
constexpr int GEMM_SMEM = NST * STAGE_FLTS * 4;  // 131072 B

__global__ void __launch_bounds__(256, 1)
k_gemm(const float* __restrict__ Bw, const float* __restrict__ bias) {
    extern __shared__ float sm[];
    const int tid = threadIdx.x;
    const int lane = tid & 31, wid = tid >> 5;
    const int wm = wid & 1, wn = wid >> 1;      // 2 x 4 warp grid
    const int g = lane >> 2, l4 = lane & 3;
    const int mt = blockIdx.x;                   // m-tile 0..3
    const int m0 = mt * BM, n0 = blockIdx.y * BN;
    const uint32_t sbase = smem_u32(sm);

    float acc[4][4][4];
#pragma unroll
    for (int i = 0; i < 4; i++)
#pragma unroll
        for (int j = 0; j < 4; j++)
#pragma unroll
            for (int q = 0; q < 4; q++) acc[i][j][q] = 0.f;

    auto load_tile = [&](int c, int s) {
        uint32_t sa = sbase + s * STAGE_FLTS * 4;
        uint32_t sb = sa + 4096 * 4;
        const float* asrc = g_At2 + (size_t)(mt * 16 + c) * 4096;
        // A: 4096 floats = 1024 linear 16B chunks
#pragma unroll
        for (int i = 0; i < 4; i++) {
            int ch = tid + i * 256;
            CP16(sa + ch * 16, asrc + ch * 4);
        }
        // B: 4096 elems, 4B each, direct from Wg, scattered into interleave
#pragma unroll
        for (int i = 0; i < 16; i++) {
            int e = tid + i * 256;
            int k = e >> 7, n = e & 127;
            int gn = n0 + n;
            if (gn >= kV) gn = kV - 1;  // clamped garbage, never used
            int off = (((k >> 3) * 128 + n) * 4 + (k & 3)) * 2 + ((k >> 2) & 1);
            CP4(sb + off * 4, Bw + (size_t)(c * KC + k) * kV + gn);
        }
    };

#pragma unroll
    for (int s = 0; s < NST; s++) { load_tile(s, s); CPCOMMIT(); }

#pragma unroll 1
    for (int kt = 0; kt < NKT; kt++) {
        int s = kt % NST;
        CPWAIT();
        __syncthreads();
        const float4* As = (const float4*)(sm + s * STAGE_FLTS);
        const float2* Bs = (const float2*)(sm + s * STAGE_FLTS + 4096);
#pragma unroll
        for (int ks = 0; ks < 4; ks++) {
            float4 av[4];
            float2 bv[4];
#pragma unroll
            for (int mf = 0; mf < 4; mf++)
                av[mf] = As[((ks * 8 + wm * 4 + mf) * 8 + g) * 4 + l4];
#pragma unroll
            for (int nf = 0; nf < 4; nf++)
                bv[nf] = Bs[(ks * 128 + wn * 32 + nf * 8 + g) * 4 + l4];
#pragma unroll
            for (int mf = 0; mf < 4; mf++)
#pragma unroll
                for (int nf = 0; nf < 4; nf++)
                    mma_tf32(acc[mf][nf], av[mf], bv[nf]);
        }
        __syncthreads();
        if (kt + NST < NKT) load_tile(kt + NST, s);
        CPCOMMIT();
    }
    __syncthreads();

    // ---------- epilogue: bias + store + per-(row, n-tile) partial stats ----------
    float* s_m = sm;           // [128][4]
    float* s_s = sm + 512;
    float bv[4][2];
#pragma unroll
    for (int nf = 0; nf < 4; nf++) {
        int n = n0 + wn * 32 + nf * 8 + l4 * 2;
        bv[nf][0] = (n < kV) ? __ldg(bias + n) : 0.f;
        bv[nf][1] = (n + 1 < kV) ? __ldg(bias + n + 1) : 0.f;
    }
#pragma unroll
    for (int mf = 0; mf < 4; mf++) {
#pragma unroll
        for (int h = 0; h < 2; h++) {
            int rowb = wm * 64 + mf * 16 + g + h * 8;
            size_t rbase = (size_t)(m0 + rowb) * kV;
            float vv[8];
            float mx = -INFINITY;
#pragma unroll
            for (int nf = 0; nf < 4; nf++) {
                int n = n0 + wn * 32 + nf * 8 + l4 * 2;
                float x0 = acc[mf][nf][h * 2 + 0] + bv[nf][0];
                float x1 = acc[mf][nf][h * 2 + 1] + bv[nf][1];
                if (n < kV)     { g_logits[rbase + n] = x0;     mx = fmaxf(mx, x0); }
                else x0 = -INFINITY;
                if (n + 1 < kV) { g_logits[rbase + n + 1] = x1; mx = fmaxf(mx, x1); }
                else x1 = -INFINITY;
                vv[nf * 2] = x0; vv[nf * 2 + 1] = x1;
            }
            mx = fmaxf(mx, __shfl_xor_sync(0xffffffffu, mx, 1));
            mx = fmaxf(mx, __shfl_xor_sync(0xffffffffu, mx, 2));
            float sum = 0.f;
            if (mx > -INFINITY) {
#pragma unroll
                for (int j = 0; j < 8; j++) sum += __expf(vv[j] - mx);
            }
            sum += __shfl_xor_sync(0xffffffffu, sum, 1);
            sum += __shfl_xor_sync(0xffffffffu, sum, 2);
            if (l4 == 0) { s_m[rowb * 4 + wn] = mx; s_s[rowb * 4 + wn] = sum; }
        }
    }
    __syncthreads();
    if (tid < 128) {
        float mx = -INFINITY, sum = 0.f;
#pragma unroll
        for (int w = 0; w < 4; w++) {
            float m2 = s_m[tid * 4 + w], s2 = s_s[tid * 4 + w];
            if (m2 > mx) { sum = sum * __expf(mx - m2) + s2; mx = m2; }
            else         { sum += s2 * __expf(m2 - mx); }
        }
        g_pmax[(size_t)blockIdx.y * kM + m0 + tid] = mx;
        g_psum[(size_t)blockIdx.y * kM + m0 + tid] = sum;
    }
}

// ======================= final row-stats reduce =======================
__global__ void k_rowfin() {
    int row = blockIdx.x;
    int lane = threadIdx.x;
    float mx = -INFINITY, sum = 0.f;
    for (int y = lane; y < NYB; y += 32) {
        float m2 = g_pmax[(size_t)y * kM + row], s2 = g_psum[(size_t)y * kM + row];
        if (m2 > mx) { sum = sum * __expf(mx - m2) + s2; mx = m2; }
        else         { sum += s2 * __expf(m2 - mx); }
    }
#pragma unroll
    for (int o = 16; o > 0; o >>= 1) {
        float m2 = __shfl_xor_sync(0xffffffffu, mx, o);
        float s2 = __shfl_xor_sync(0xffffffffu, sum, o);
        if (m2 > mx) { sum = sum * __expf(mx - m2) + s2; mx = m2; }
        else         { sum += s2 * __expf(m2 - mx); }
    }
    if (lane == 0) { g_rowmax[row] = mx; g_rowsum[row] = sum; }
}

// ======================= q[s,b] = memory[s,b,:] . W_prob =======================
__global__ void k_q(const float* __restrict__ mem, const float* __restrict__ Wp) {
    int row = blockIdx.x * 4 + (threadIdx.x >> 5);
    int lane = threadIdx.x & 31;
    const float* r = mem + (size_t)row * kH;
    float acc = 0.f;
#pragma unroll 4
    for (int h = lane; h < kH; h += 32) acc = fmaf(r[h], Wp[h], acc);
#pragma unroll
    for (int o = 16; o > 0; o >>= 1) acc += __shfl_down_sync(0xffffffffu, acc, o);
    if (lane == 0) g_q[row] = acc;
}

// ======================= leader flags =======================
__global__ void k_leader(const int* __restrict__ src) {
    int b = blockIdx.x;
    int s = threadIdx.x;
    __shared__ int tok[kS];
    tok[s] = src[(size_t)s * kB + b];
    __syncthreads();
    int me = tok[s];
    int lead = 1;
    for (int j = 0; j < s; j++)
        if (tok[j] == me) { lead = 0; break; }
    g_leader[b * kS + s] = lead;
}

// ======================= Z_c + p_gen per (t,b) =======================
__global__ void k_zc(const int* __restrict__ src, const float* __restrict__ attn,
                     const float* __restrict__ bp) {
    int m = blockIdx.x;
    int t = m / kB, b = m % kB;
    __shared__ float a_sh[kS];
    __shared__ int tok[kS];
    __shared__ float r1[kS], r2[kS], r3[kS];
    int s = threadIdx.x;
    float av = attn[((size_t)b * kT + t) * kS + s];
    a_sh[s] = av;
    tok[s] = src[(size_t)s * kB + b];
    r3[s] = av * g_q[s * kB + b];
    __syncthreads();
    float val = 0.f, cnt = 0.f;
    if (g_leader[b * kS + s]) {
        float c = 0.f;
        int me = tok[s];
        for (int j = 0; j < kS; j++)
            if (tok[j] == me) c += a_sh[j];
        val = expf(c);
        cnt = 1.f;
    }
    r1[s] = val; r2[s] = cnt;
    __syncthreads();
    for (int off = kS / 2; off > 0; off >>= 1) {
        if (s < off) { r1[s] += r1[s + off]; r2[s] += r2[s + off]; r3[s] += r3[s + off]; }
        __syncthreads();
    }
    if (s == 0) {
        g_zc[m] = ((float)kV - r2[0]) + r1[0];
        float z = r3[0] + bp[0];
        g_prob[m] = 1.f / (1.f + expf(-z));
    }
}

// ======================= single-pass dense output =======================
__global__ void k_logmix(float* __restrict__ out) {
    int m = blockIdx.y;
    int v = blockIdx.x * 256 + threadIdx.x;
    if (v >= kV) return;
    float p = g_prob[m];
    float sgen = p / g_rowsum[m];
    float mxv = g_rowmax[m];
    float scopy = (1.f - p) / g_zc[m];
    float gl = g_logits[(size_t)m * kV + v];
    out[(size_t)m * kV + v] = logf(fmaf(sgen, __expf(gl - mxv), scopy));
}

// ======================= sparse copy fixup =======================
__global__ void k_fix(const int* __restrict__ src, const float* __restrict__ attn,
                      float* __restrict__ out) {
    int m = blockIdx.x;
    int t = m / kB, b = m % kB;
    __shared__ float a_sh[kS];
    __shared__ int tok[kS];
    int s = threadIdx.x;
    a_sh[s] = attn[((size_t)b * kT + t) * kS + s];
    tok[s] = src[(size_t)s * kB + b];
    __syncthreads();
    if (!g_leader[b * kS + s]) return;
    int vv = tok[s];
    float c = 0.f;
    for (int j = 0; j < kS; j++)
        if (tok[j] == vv) c += a_sh[j];
    float p = g_prob[m];
    float sgen = p / g_rowsum[m];
    float mxv = g_rowmax[m];
    float scopy = (1.f - p) / g_zc[m];
    float gl = g_logits[(size_t)m * kV + vv];
    out[(size_t)m * kV + vv] = logf(fmaf(sgen, __expf(gl - mxv), scopy * expf(c)));
}

extern "C" void kernel_launch(void* const* d_in, const int* in_sizes, int n_in,
                              void* d_out, int out_size) {
    const int*   src  = (const int*)d_in[0];    // src_full [S,B] int32
    const float* dec  = (const float*)d_in[1];  // decode_output [T,B,H]
    const float* attn = (const float*)d_in[2];  // decode_attn [B,T,S]
    const float* mem  = (const float*)d_in[3];  // memory [S,B,H]
    const float* Wg   = (const float*)d_in[4];  // W_gen [H,V]
    const float* bg   = (const float*)d_in[5];  // b_gen [V]
    const float* Wp   = (const float*)d_in[6];  // W_prob [H]
    const float* bp   = (const float*)d_in[7];  // b_prob [1]
    float* out = (float*)d_out;                 // [T,B,V] f32

    cudaFuncSetAttribute(k_gemm, cudaFuncAttributeMaxDynamicSharedMemorySize, GEMM_SMEM);

    k_at<<<(kH * kM) / 256, 256>>>(dec);
    k_leader<<<kB, kS>>>(src);
    k_q<<<(kS * kB) / 4, 128>>>(mem, Wp);
    k_zc<<<kM, kS>>>(src, attn, bp);
    k_gemm<<<dim3(kM / BM, NYB), 256, GEMM_SMEM>>>(Wg, bg);
    k_rowfin<<<kM, 32>>>();
    k_logmix<<<dim3((kV + 255) / 256, kM), 256>>>(out);
    k_fix<<<kM, kS>>>(src, attn, out);
}

// round 5
// speedup vs baseline: 1.4819x; 1.4819x over previous
#include <cuda_runtime.h>
#include <math.h>
#include <stdint.h>

// Problem constants
constexpr int kV = 50257;
constexpr int kH = 512;
constexpr int kS = 512;
constexpr int kB = 8;
constexpr int kT = 64;
constexpr int kM = kT * kB;          // 512 rows (t*B+b)
constexpr int NYB = 393;             // n-tiles of 128 -> 393*128 = 50304

// Scratch (device globals — allocation-free per harness rules)
__device__ float g_logits[(size_t)kM * kV];      // ~103 MB
__device__ float g_Bp2[(size_t)NYB * 16 * 4096]; // pre-tiled interleaved W_gen ~103 MB
__device__ float g_At2[kH * kM];                 // pre-tiled fragment-interleaved A (tf32)
__device__ float g_csum[(size_t)kM * kS];        // group-summed attn per (m, leader s)
__device__ float g_pmax[(size_t)NYB * kM];
__device__ float g_psum[(size_t)NYB * kM];
__device__ float g_prob[kM];
__device__ float g_rowmax[kM];
__device__ float g_rowsum[kM];
__device__ float g_zc[kM];
__device__ float g_q[kS * kB];
__device__ int   g_gid[kB * kS];

// ======================= helpers =======================
__device__ __forceinline__ float to_tf32(float x) {
    float r;
    asm("cvt.rna.tf32.f32 %0, %1;" : "=f"(r) : "f"(x));
    return r;
}
__device__ __forceinline__ uint32_t smem_u32(const void* p) {
    uint32_t a;
    asm("{ .reg .u64 t; cvta.to.shared.u64 t, %1; cvt.u32.u64 %0, t; }" : "=r"(a) : "l"(p));
    return a;
}
#define CP16(dst, src) \
    asm volatile("cp.async.cg.shared.global [%0], [%1], 16;" :: "r"(dst), "l"(src))
#define CPCOMMIT() asm volatile("cp.async.commit_group;" ::: "memory")
#define CPWAIT()   asm volatile("cp.async.wait_group 3;" ::: "memory")

__device__ __forceinline__ void mma_tf32(float* c, const float4& a, const float2& b) {
    asm volatile(
        "mma.sync.aligned.m16n8k8.row.col.f32.tf32.tf32.f32 "
        "{%0,%1,%2,%3}, {%4,%5,%6,%7}, {%8,%9}, {%0,%1,%2,%3};"
        : "+f"(c[0]), "+f"(c[1]), "+f"(c[2]), "+f"(c[3])
        : "r"(__float_as_uint(a.x)), "r"(__float_as_uint(a.y)),
          "r"(__float_as_uint(a.z)), "r"(__float_as_uint(a.w)),
          "r"(__float_as_uint(b.x)), "r"(__float_as_uint(b.y)));
}

// ======================= pre-pass: A -> pre-tiled fragment-interleaved (tf32) =======================
__global__ void k_at(const float* __restrict__ A) {
    int idx = blockIdx.x * 256 + threadIdx.x;   // over kH*kM = 262144
    int m = idx >> 9, k = idx & 511;
    float v = to_tf32(A[(size_t)m * kH + k]);
    int mt = m >> 7, mm = m & 127;
    int ct = k >> 5, kk = k & 31;
    int kg = kk >> 3, l4 = kk & 3, hi = (kk >> 2) & 1;
    int off = (((kg * 8 + (mm >> 4)) * 8 + (mm & 7)) * 4 + l4) * 4 + hi * 2 + ((mm >> 3) & 1);
    g_At2[(size_t)(mt * 16 + ct) * 4096 + off] = v;
}

// ======================= pre-pass: W_gen -> pre-tiled fragment-interleaved =======================
// Per (nt, kt): 32(k) x 128(n) tile; out offset o encodes hi=o&1, l4=(o>>1)&3,
// n=(o>>3)&127, ks=o>>10, with k = ks*8 + hi*4 + l4. Both GMEM sides coalesced.
__global__ void __launch_bounds__(256) k_bpad2(const float* __restrict__ Bw) {
    __shared__ float t[32][129];
    int nt = blockIdx.x, kt = blockIdx.y;
#pragma unroll
    for (int i = 0; i < 16; i++) {
        int idx = threadIdx.x + i * 256;
        int k = idx >> 7, n = idx & 127;
        int gn = nt * 128 + n;
        t[k][n] = (gn < kV) ? Bw[(size_t)(kt * 32 + k) * kV + gn] : 0.f;
    }
    __syncthreads();
    float* dst = g_Bp2 + (size_t)(nt * 16 + kt) * 4096;
#pragma unroll
    for (int i = 0; i < 16; i++) {
        int o = threadIdx.x + i * 256;
        int hi = o & 1, l4 = (o >> 1) & 3, n = (o >> 3) & 127, ks = o >> 10;
        dst[o] = t[ks * 8 + hi * 4 + l4][n];
    }
}

// ======================= GEMM: logits = A @ W + bias (mma.sync tf32) =======================
constexpr int BM = 128, BN = 128;
constexpr int NST = 4;
constexpr int NKT = 16;                   // k-tiles of 32
constexpr int STAGE_FLTS = 8192;          // A 4096 + B 4096
constexpr int GEMM_SMEM = NST * STAGE_FLTS * 4;  // 131072 B

__global__ void __launch_bounds__(256, 1)
k_gemm(const float* __restrict__ bias) {
    extern __shared__ float sm[];
    const int tid = threadIdx.x;
    const int lane = tid & 31, wid = tid >> 5;
    const int wm = wid & 1, wn = wid >> 1;      // 2 x 4 warp grid
    const int g = lane >> 2, l4 = lane & 3;
    const int mt = blockIdx.x;
    const int m0 = mt * BM, n0 = blockIdx.y * BN;
    const uint32_t sbase = smem_u32(sm);

    float acc[4][4][4];
#pragma unroll
    for (int i = 0; i < 4; i++)
#pragma unroll
        for (int j = 0; j < 4; j++)
#pragma unroll
            for (int q = 0; q < 4; q++) acc[i][j][q] = 0.f;

    auto load_tile = [&](int c, int s) {
        uint32_t sa = sbase + s * STAGE_FLTS * 4;
        const float* asrc = g_At2 + (size_t)(mt * 16 + c) * 4096;
        const float* bsrc = g_Bp2 + (size_t)(blockIdx.y * 16 + c) * 4096;
#pragma unroll
        for (int i = 0; i < 4; i++) {
            int ch = tid + i * 256;
            CP16(sa + ch * 16, asrc + ch * 4);
        }
#pragma unroll
        for (int i = 0; i < 4; i++) {
            int ch = tid + i * 256;
            CP16(sa + 16384 + ch * 16, bsrc + ch * 4);
        }
    };

#pragma unroll
    for (int s = 0; s < NST; s++) { load_tile(s, s); CPCOMMIT(); }

#pragma unroll 1
    for (int kt = 0; kt < NKT; kt++) {
        int s = kt % NST;
        CPWAIT();
        __syncthreads();
        const float4* As = (const float4*)(sm + s * STAGE_FLTS);
        const float2* Bs = (const float2*)(sm + s * STAGE_FLTS + 4096);
#pragma unroll
        for (int ks = 0; ks < 4; ks++) {
            float4 av[4];
            float2 bv[4];
#pragma unroll
            for (int mf = 0; mf < 4; mf++)
                av[mf] = As[((ks * 8 + wm * 4 + mf) * 8 + g) * 4 + l4];
#pragma unroll
            for (int nf = 0; nf < 4; nf++)
                bv[nf] = Bs[(ks * 128 + wn * 32 + nf * 8 + g) * 4 + l4];
#pragma unroll
            for (int mf = 0; mf < 4; mf++)
#pragma unroll
                for (int nf = 0; nf < 4; nf++)
                    mma_tf32(acc[mf][nf], av[mf], bv[nf]);
        }
        __syncthreads();
        if (kt + NST < NKT) load_tile(kt + NST, s);
        CPCOMMIT();
    }
    __syncthreads();

    // ---------- epilogue: bias + store + per-(row, n-tile) partial stats ----------
    float* s_m = sm;           // [128][4]
    float* s_s = sm + 512;
    float bv[4][2];
#pragma unroll
    for (int nf = 0; nf < 4; nf++) {
        int n = n0 + wn * 32 + nf * 8 + l4 * 2;
        bv[nf][0] = (n < kV) ? __ldg(bias + n) : 0.f;
        bv[nf][1] = (n + 1 < kV) ? __ldg(bias + n + 1) : 0.f;
    }
#pragma unroll
    for (int mf = 0; mf < 4; mf++) {
#pragma unroll
        for (int h = 0; h < 2; h++) {
            int rowb = wm * 64 + mf * 16 + g + h * 8;
            size_t rbase = (size_t)(m0 + rowb) * kV;
            float vv[8];
            float mx = -INFINITY;
#pragma unroll
            for (int nf = 0; nf < 4; nf++) {
                int n = n0 + wn * 32 + nf * 8 + l4 * 2;
                float x0 = acc[mf][nf][h * 2 + 0] + bv[nf][0];
                float x1 = acc[mf][nf][h * 2 + 1] + bv[nf][1];
                if (n < kV)     { g_logits[rbase + n] = x0;     mx = fmaxf(mx, x0); }
                else x0 = -INFINITY;
                if (n + 1 < kV) { g_logits[rbase + n + 1] = x1; mx = fmaxf(mx, x1); }
                else x1 = -INFINITY;
                vv[nf * 2] = x0; vv[nf * 2 + 1] = x1;
            }
            mx = fmaxf(mx, __shfl_xor_sync(0xffffffffu, mx, 1));
            mx = fmaxf(mx, __shfl_xor_sync(0xffffffffu, mx, 2));
            float sum = 0.f;
            if (mx > -INFINITY) {
#pragma unroll
                for (int j = 0; j < 8; j++) sum += __expf(vv[j] - mx);
            }
            sum += __shfl_xor_sync(0xffffffffu, sum, 1);
            sum += __shfl_xor_sync(0xffffffffu, sum, 2);
            if (l4 == 0) { s_m[rowb * 4 + wn] = mx; s_s[rowb * 4 + wn] = sum; }
        }
    }
    __syncthreads();
    if (tid < 128) {
        float mx = -INFINITY, sum = 0.f;
#pragma unroll
        for (int w = 0; w < 4; w++) {
            float m2 = s_m[tid * 4 + w], s2 = s_s[tid * 4 + w];
            if (m2 > mx) { sum = sum * __expf(mx - m2) + s2; mx = m2; }
            else         { sum += s2 * __expf(m2 - mx); }
        }
        g_pmax[(size_t)blockIdx.y * kM + m0 + tid] = mx;
        g_psum[(size_t)blockIdx.y * kM + m0 + tid] = sum;
    }
}

// ======================= final row-stats reduce =======================
__global__ void k_rowfin() {
    int row = blockIdx.x;
    int lane = threadIdx.x;
    float mx = -INFINITY, sum = 0.f;
    for (int y = lane; y < NYB; y += 32) {
        float m2 = g_pmax[(size_t)y * kM + row], s2 = g_psum[(size_t)y * kM + row];
        if (m2 > mx) { sum = sum * __expf(mx - m2) + s2; mx = m2; }
        else         { sum += s2 * __expf(m2 - mx); }
    }
#pragma unroll
    for (int o = 16; o > 0; o >>= 1) {
        float m2 = __shfl_xor_sync(0xffffffffu, mx, o);
        float s2 = __shfl_xor_sync(0xffffffffu, sum, o);
        if (m2 > mx) { sum = sum * __expf(mx - m2) + s2; mx = m2; }
        else         { sum += s2 * __expf(m2 - mx); }
    }
    if (lane == 0) { g_rowmax[row] = mx; g_rowsum[row] = sum; }
}

// ======================= q[s,b] = memory[s,b,:] . W_prob =======================
__global__ void k_q(const float* __restrict__ mem, const float* __restrict__ Wp) {
    int row = blockIdx.x * 4 + (threadIdx.x >> 5);
    int lane = threadIdx.x & 31;
    const float* r = mem + (size_t)row * kH;
    float acc = 0.f;
#pragma unroll 4
    for (int h = lane; h < kH; h += 32) acc = fmaf(r[h], Wp[h], acc);
#pragma unroll
    for (int o = 16; o > 0; o >>= 1) acc += __shfl_down_sync(0xffffffffu, acc, o);
    if (lane == 0) g_q[row] = acc;
}

// ======================= leader/group-id flags =======================
__global__ void k_leader(const int* __restrict__ src) {
    int b = blockIdx.x;
    int s = threadIdx.x;
    __shared__ int tok[kS];
    tok[s] = src[(size_t)s * kB + b];
    __syncthreads();
    int me = tok[s];
    int gid = s;
    for (int j = 0; j < s; j++)
        if (tok[j] == me) { gid = j; break; }
    g_gid[b * kS + s] = gid;
}

// ======================= Z_c + p_gen per (t,b) =======================
__global__ void k_zc(const float* __restrict__ attn, const float* __restrict__ bp) {
    int m = blockIdx.x;
    int t = m / kB, b = m % kB;
    __shared__ float grp[kS];
    __shared__ float r1[kS], r2[kS], r3[kS];
    int s = threadIdx.x;
    float av = attn[((size_t)b * kT + t) * kS + s];
    int gid = g_gid[b * kS + s];
    grp[s] = 0.f;
    r3[s] = av * g_q[s * kB + b];
    __syncthreads();
    atomicAdd(&grp[gid], av);
    __syncthreads();
    float val = 0.f, cnt = 0.f;
    if (gid == s) {
        float c = grp[s];
        g_csum[(size_t)m * kS + s] = c;
        val = expf(c);
        cnt = 1.f;
    }
    r1[s] = val; r2[s] = cnt;
    __syncthreads();
    for (int off = kS / 2; off > 0; off >>= 1) {
        if (s < off) { r1[s] += r1[s + off]; r2[s] += r2[s + off]; r3[s] += r3[s + off]; }
        __syncthreads();
    }
    if (s == 0) {
        g_zc[m] = ((float)kV - r2[0]) + r1[0];
        float z = r3[0] + bp[0];
        g_prob[m] = 1.f / (1.f + expf(-z));
    }
}

// ======================= single-pass dense output (vectorized) =======================
__global__ void k_logmix(float* __restrict__ out) {
    int m = blockIdx.y;
    size_t base = (size_t)m * kV;
    int head = (int)((4 - (base & 3)) & 3);
    int nv4 = (kV - head) >> 2;
    int tail = kV - head - nv4 * 4;

    float p = g_prob[m];
    float sgen = p / g_rowsum[m];
    float mxv = g_rowmax[m];
    float scopy = (1.f - p) / g_zc[m];

    const float4* L4 = (const float4*)(g_logits + base + head);
    float4* O4 = (float4*)(out + base + head);
    for (int i = blockIdx.x * 256 + threadIdx.x; i < nv4; i += gridDim.x * 256) {
        float4 v = L4[i];
        v.x = __logf(fmaf(sgen, __expf(v.x - mxv), scopy));
        v.y = __logf(fmaf(sgen, __expf(v.y - mxv), scopy));
        v.z = __logf(fmaf(sgen, __expf(v.z - mxv), scopy));
        v.w = __logf(fmaf(sgen, __expf(v.w - mxv), scopy));
        O4[i] = v;
    }
    if (blockIdx.x == 0 && threadIdx.x < (unsigned)(head + tail)) {
        int v = (threadIdx.x < (unsigned)head) ? (int)threadIdx.x
                                               : head + nv4 * 4 + ((int)threadIdx.x - head);
        float gl = g_logits[base + v];
        out[base + v] = __logf(fmaf(sgen, __expf(gl - mxv), scopy));
    }
}

// ======================= sparse copy fixup =======================
__global__ void k_fix(const int* __restrict__ src, float* __restrict__ out) {
    int m = blockIdx.x;
    int b = m % kB;
    int s = threadIdx.x;
    if (g_gid[b * kS + s] != s) return;   // leaders only
    int vv = src[(size_t)s * kB + b];
    float c = g_csum[(size_t)m * kS + s];
    float p = g_prob[m];
    float sgen = p / g_rowsum[m];
    float mxv = g_rowmax[m];
    float scopy = (1.f - p) / g_zc[m];
    float gl = g_logits[(size_t)m * kV + vv];
    out[(size_t)m * kV + vv] = __logf(fmaf(sgen, __expf(gl - mxv), scopy * __expf(c)));
}

extern "C" void kernel_launch(void* const* d_in, const int* in_sizes, int n_in,
                              void* d_out, int out_size) {
    const int*   src  = (const int*)d_in[0];    // src_full [S,B] int32
    const float* dec  = (const float*)d_in[1];  // decode_output [T,B,H]
    const float* attn = (const float*)d_in[2];  // decode_attn [B,T,S]
    const float* mem  = (const float*)d_in[3];  // memory [S,B,H]
    const float* Wg   = (const float*)d_in[4];  // W_gen [H,V]
    const float* bg   = (const float*)d_in[5];  // b_gen [V]
    const float* Wp   = (const float*)d_in[6];  // W_prob [H]
    const float* bp   = (const float*)d_in[7];  // b_prob [1]
    float* out = (float*)d_out;                 // [T,B,V] f32

    cudaFuncSetAttribute(k_gemm, cudaFuncAttributeMaxDynamicSharedMemorySize, GEMM_SMEM);

    k_at<<<(kH * kM) / 256, 256>>>(dec);
    k_bpad2<<<dim3(NYB, 16), 256>>>(Wg);
    k_leader<<<kB, kS>>>(src);
    k_q<<<(kS * kB) / 4, 128>>>(mem, Wp);
    k_zc<<<kM, kS>>>(attn, bp);
    k_gemm<<<dim3(kM / BM, NYB), 256, GEMM_SMEM>>>(bg);
    k_rowfin<<<kM, 32>>>();
    k_logmix<<<dim3(13, kM), 256>>>(out);
    k_fix<<<kM, kS>>>(src, out);
}

// round 6
// speedup vs baseline: 2.2714x; 1.5328x over previous
#include <cuda_runtime.h>
#include <math.h>
#include <stdint.h>

// Problem constants
constexpr int kV = 50257;
constexpr int kH = 512;
constexpr int kS = 512;
constexpr int kB = 8;
constexpr int kT = 64;
constexpr int kM = kT * kB;          // 512 rows (t*B+b)
constexpr int NYB = 393;             // n-tiles of 128 -> 393*128 = 50304

// Scratch (device globals — allocation-free per harness rules)
__device__ float    g_logits[(size_t)kM * kV];        // ~103 MB
__device__ uint32_t g_Bp2h[(size_t)NYB * 16 * 2048];  // pre-tiled bf16 W_gen ~51.5 MB
__device__ uint32_t g_At2h[(kH * kM) / 2];            // pre-tiled bf16 A
__device__ float    g_csum[(size_t)kM * kS];
__device__ float    g_pmax[(size_t)NYB * kM];
__device__ float    g_psum[(size_t)NYB * kM];
__device__ float    g_prob[kM];
__device__ float    g_rowmax[kM];
__device__ float    g_rowsum[kM];
__device__ float    g_zc[kM];
__device__ float    g_q[kS * kB];
__device__ int      g_gid[kB * kS];

// ======================= helpers =======================
__device__ __forceinline__ uint32_t pack_bf16(float lo, float hi) {
    uint32_t r;
    asm("cvt.rn.bf16x2.f32 %0, %1, %2;" : "=r"(r) : "f"(hi), "f"(lo));
    return r;
}
__device__ __forceinline__ uint32_t smem_u32(const void* p) {
    uint32_t a;
    asm("{ .reg .u64 t; cvta.to.shared.u64 t, %1; cvt.u32.u64 %0, t; }" : "=r"(a) : "l"(p));
    return a;
}
#define CP16(dst, src) \
    asm volatile("cp.async.cg.shared.global [%0], [%1], 16;" :: "r"(dst), "l"(src))
#define CPCOMMIT() asm volatile("cp.async.commit_group;" ::: "memory")
#define CPWAIT()   asm volatile("cp.async.wait_group 3;" ::: "memory")

__device__ __forceinline__ void mma_bf16(float* c, const uint4& a, const uint2& b) {
    asm volatile(
        "mma.sync.aligned.m16n8k16.row.col.f32.bf16.bf16.f32 "
        "{%0,%1,%2,%3}, {%4,%5,%6,%7}, {%8,%9}, {%0,%1,%2,%3};"
        : "+f"(c[0]), "+f"(c[1]), "+f"(c[2]), "+f"(c[3])
        : "r"(a.x), "r"(a.y), "r"(a.z), "r"(a.w), "r"(b.x), "r"(b.y));
}

// ======================= pre-pass: A -> bf16 fragment-interleaved =======================
// Per (mt,kt) tile: 2048 words. cell (ks2*8+mi)*32+lane holds float4 {a0,a1,a2,a3}.
// a0:(g,2l4) a1:(g+8,2l4) a2:(g,2l4+8) a3:(g+8,2l4+8); word = pair (k, k+1).
__global__ void k_at(const float* __restrict__ A) {
    int widx = blockIdx.x * 256 + threadIdx.x;  // 131072 words
    int tile = widx >> 11, within = widx & 2047;
    int mt = tile >> 4, kt = tile & 15;
    int w = within & 3;
    int lane = (within >> 2) & 31;
    int blk = within >> 7;                       // 0..15
    int ks2 = blk >> 3, mi = blk & 7;
    int g = lane >> 2, l4 = lane & 3;
    int m = mt * 128 + mi * 16 + (w & 1) * 8 + g;
    int k = kt * 32 + ks2 * 16 + ((w >> 1) & 1) * 8 + l4 * 2;
    const float* ap = A + (size_t)m * kH + k;
    g_At2h[widx] = pack_bf16(ap[0], ap[1]);
}

// ======================= pre-pass: W_gen -> bf16 fragment-interleaved =======================
// Per (nt,kt) tile: 2048 words. cell (ks2*16+nb)*32+lane holds float2 {b0,b1}.
// b0 = {B[2l4][g], B[2l4+1][g]}, b1 = {B[2l4+8][g], B[2l4+9][g]} (k-rows, n-col within nb).
__global__ void __launch_bounds__(256) k_bpad2(const float* __restrict__ Bw) {
    __shared__ float t[32][129];
    int nt = blockIdx.x, kt = blockIdx.y;
#pragma unroll
    for (int i = 0; i < 16; i++) {
        int idx = threadIdx.x + i * 256;
        int k = idx >> 7, n = idx & 127;
        int gn = nt * 128 + n;
        t[k][n] = (gn < kV) ? Bw[(size_t)(kt * 32 + k) * kV + gn] : 0.f;
    }
    __syncthreads();
    uint32_t* dst = g_Bp2h + (size_t)(nt * 16 + kt) * 2048;
#pragma unroll
    for (int i = 0; i < 8; i++) {
        int o = threadIdx.x + i * 256;
        int wsel = o & 1;
        int lane = (o >> 1) & 31;
        int nb = (o >> 6) & 15;
        int ks2 = o >> 10;
        int g = lane >> 2, l4 = lane & 3;
        int k0 = ks2 * 16 + l4 * 2 + wsel * 8;
        int nloc = nb * 8 + g;
        dst[((ks2 * 16 + nb) * 32 + lane) * 2 + wsel] = pack_bf16(t[k0][nloc], t[k0 + 1][nloc]);
    }
}

// ======================= GEMM: logits = A @ W + bias (mma.sync bf16) =======================
constexpr int BM = 128, BN = 128;
constexpr int NST = 4;
constexpr int NKT = 16;                     // k-tiles of 32
constexpr int STAGE_WORDS = 4096;           // A 2048 + B 2048 (uint32)
constexpr int GEMM_SMEM = NST * STAGE_WORDS * 4;  // 65536 B

__global__ void __launch_bounds__(256, 1)
k_gemm(const float* __restrict__ bias) {
    extern __shared__ uint32_t sm[];
    const int tid = threadIdx.x;
    const int lane = tid & 31, wid = tid >> 5;
    const int wm = wid & 1, wn = wid >> 1;      // 2 x 4 warp grid
    const int g = lane >> 2, l4 = lane & 3;
    const int mt = blockIdx.x;
    const int m0 = mt * BM, n0 = blockIdx.y * BN;
    const uint32_t sbase = smem_u32(sm);

    float acc[4][4][4];
#pragma unroll
    for (int i = 0; i < 4; i++)
#pragma unroll
        for (int j = 0; j < 4; j++)
#pragma unroll
            for (int q = 0; q < 4; q++) acc[i][j][q] = 0.f;

    auto load_tile = [&](int c, int s) {
        uint32_t sa = sbase + s * STAGE_WORDS * 4;
        const uint32_t* asrc = g_At2h + (size_t)(mt * 16 + c) * 2048;
        const uint32_t* bsrc = g_Bp2h + (size_t)(blockIdx.y * 16 + c) * 2048;
#pragma unroll
        for (int i = 0; i < 2; i++) {
            int ch = tid + i * 256;             // 512 float4 chunks each
            CP16(sa + ch * 16, asrc + ch * 4);
            CP16(sa + 8192 + ch * 16, bsrc + ch * 4);
        }
    };

#pragma unroll
    for (int s = 0; s < NST; s++) { load_tile(s, s); CPCOMMIT(); }

#pragma unroll 1
    for (int kt = 0; kt < NKT; kt++) {
        int s = kt % NST;
        CPWAIT();
        __syncthreads();
        const uint4* As = (const uint4*)(sm + s * STAGE_WORDS);
        const uint2* Bs = (const uint2*)(sm + s * STAGE_WORDS + 2048);
#pragma unroll
        for (int ks2 = 0; ks2 < 2; ks2++) {
            uint4 av[4];
            uint2 bv[4];
#pragma unroll
            for (int mf = 0; mf < 4; mf++)
                av[mf] = As[(ks2 * 8 + wm * 4 + mf) * 32 + lane];
#pragma unroll
            for (int nf = 0; nf < 4; nf++)
                bv[nf] = Bs[(ks2 * 16 + wn * 4 + nf) * 32 + lane];
#pragma unroll
            for (int mf = 0; mf < 4; mf++)
#pragma unroll
                for (int nf = 0; nf < 4; nf++)
                    mma_bf16(acc[mf][nf], av[mf], bv[nf]);
        }
        __syncthreads();
        if (kt + NST < NKT) load_tile(kt + NST, s);
        CPCOMMIT();
    }
    __syncthreads();

    // ---------- epilogue: bias + store + per-(row, n-tile) partial stats ----------
    float* s_m = (float*)sm;           // [128][4]
    float* s_s = (float*)sm + 512;
    float bv[4][2];
#pragma unroll
    for (int nf = 0; nf < 4; nf++) {
        int n = n0 + wn * 32 + nf * 8 + l4 * 2;
        bv[nf][0] = (n < kV) ? __ldg(bias + n) : 0.f;
        bv[nf][1] = (n + 1 < kV) ? __ldg(bias + n + 1) : 0.f;
    }
#pragma unroll
    for (int mf = 0; mf < 4; mf++) {
#pragma unroll
        for (int h = 0; h < 2; h++) {
            int rowb = wm * 64 + mf * 16 + g + h * 8;
            size_t rbase = (size_t)(m0 + rowb) * kV;
            float vv[8];
            float mx = -INFINITY;
#pragma unroll
            for (int nf = 0; nf < 4; nf++) {
                int n = n0 + wn * 32 + nf * 8 + l4 * 2;
                float x0 = acc[mf][nf][h * 2 + 0] + bv[nf][0];
                float x1 = acc[mf][nf][h * 2 + 1] + bv[nf][1];
                if (n < kV)     { g_logits[rbase + n] = x0;     mx = fmaxf(mx, x0); }
                else x0 = -INFINITY;
                if (n + 1 < kV) { g_logits[rbase + n + 1] = x1; mx = fmaxf(mx, x1); }
                else x1 = -INFINITY;
                vv[nf * 2] = x0; vv[nf * 2 + 1] = x1;
            }
            mx = fmaxf(mx, __shfl_xor_sync(0xffffffffu, mx, 1));
            mx = fmaxf(mx, __shfl_xor_sync(0xffffffffu, mx, 2));
            float sum = 0.f;
            if (mx > -INFINITY) {
#pragma unroll
                for (int j = 0; j < 8; j++) sum += __expf(vv[j] - mx);
            }
            sum += __shfl_xor_sync(0xffffffffu, sum, 1);
            sum += __shfl_xor_sync(0xffffffffu, sum, 2);
            if (l4 == 0) { s_m[rowb * 4 + wn] = mx; s_s[rowb * 4 + wn] = sum; }
        }
    }
    __syncthreads();
    if (tid < 128) {
        float mx = -INFINITY, sum = 0.f;
#pragma unroll
        for (int w = 0; w < 4; w++) {
            float m2 = s_m[tid * 4 + w], s2 = s_s[tid * 4 + w];
            if (m2 > mx) { sum = sum * __expf(mx - m2) + s2; mx = m2; }
            else         { sum += s2 * __expf(m2 - mx); }
        }
        g_pmax[(size_t)blockIdx.y * kM + m0 + tid] = mx;
        g_psum[(size_t)blockIdx.y * kM + m0 + tid] = sum;
    }
}

// ======================= final row-stats reduce =======================
__global__ void k_rowfin() {
    int row = blockIdx.x;
    int lane = threadIdx.x;
    float mx = -INFINITY, sum = 0.f;
    for (int y = lane; y < NYB; y += 32) {
        float m2 = g_pmax[(size_t)y * kM + row], s2 = g_psum[(size_t)y * kM + row];
        if (m2 > mx) { sum = sum * __expf(mx - m2) + s2; mx = m2; }
        else         { sum += s2 * __expf(m2 - mx); }
    }
#pragma unroll
    for (int o = 16; o > 0; o >>= 1) {
        float m2 = __shfl_xor_sync(0xffffffffu, mx, o);
        float s2 = __shfl_xor_sync(0xffffffffu, sum, o);
        if (m2 > mx) { sum = sum * __expf(mx - m2) + s2; mx = m2; }
        else         { sum += s2 * __expf(m2 - mx); }
    }
    if (lane == 0) { g_rowmax[row] = mx; g_rowsum[row] = sum; }
}

// ======================= q[s,b] = memory[s,b,:] . W_prob =======================
__global__ void k_q(const float* __restrict__ mem, const float* __restrict__ Wp) {
    int row = blockIdx.x * 4 + (threadIdx.x >> 5);
    int lane = threadIdx.x & 31;
    const float* r = mem + (size_t)row * kH;
    float acc = 0.f;
#pragma unroll 4
    for (int h = lane; h < kH; h += 32) acc = fmaf(r[h], Wp[h], acc);
#pragma unroll
    for (int o = 16; o > 0; o >>= 1) acc += __shfl_down_sync(0xffffffffu, acc, o);
    if (lane == 0) g_q[row] = acc;
}

// ======================= leader/group-id flags =======================
__global__ void k_leader(const int* __restrict__ src) {
    int b = blockIdx.x;
    int s = threadIdx.x;
    __shared__ int tok[kS];
    tok[s] = src[(size_t)s * kB + b];
    __syncthreads();
    int me = tok[s];
    int gid = s;
    for (int j = 0; j < s; j++)
        if (tok[j] == me) { gid = j; break; }
    g_gid[b * kS + s] = gid;
}

// ======================= Z_c + p_gen per (t,b) =======================
__global__ void k_zc(const float* __restrict__ attn, const float* __restrict__ bp) {
    int m = blockIdx.x;
    int t = m / kB, b = m % kB;
    __shared__ float grp[kS];
    __shared__ float r1[kS], r2[kS], r3[kS];
    int s = threadIdx.x;
    float av = attn[((size_t)b * kT + t) * kS + s];
    int gid = g_gid[b * kS + s];
    grp[s] = 0.f;
    r3[s] = av * g_q[s * kB + b];
    __syncthreads();
    atomicAdd(&grp[gid], av);
    __syncthreads();
    float val = 0.f, cnt = 0.f;
    if (gid == s) {
        float c = grp[s];
        g_csum[(size_t)m * kS + s] = c;
        val = expf(c);
        cnt = 1.f;
    }
    r1[s] = val; r2[s] = cnt;
    __syncthreads();
    for (int off = kS / 2; off > 0; off >>= 1) {
        if (s < off) { r1[s] += r1[s + off]; r2[s] += r2[s + off]; r3[s] += r3[s + off]; }
        __syncthreads();
    }
    if (s == 0) {
        g_zc[m] = ((float)kV - r2[0]) + r1[0];
        float z = r3[0] + bp[0];
        g_prob[m] = 1.f / (1.f + expf(-z));
    }
}

// ======================= single-pass dense output (vectorized) =======================
__global__ void k_logmix(float* __restrict__ out) {
    int m = blockIdx.y;
    size_t base = (size_t)m * kV;
    int head = (int)((4 - (base & 3)) & 3);
    int nv4 = (kV - head) >> 2;
    int tail = kV - head - nv4 * 4;

    float p = g_prob[m];
    float sgen = p / g_rowsum[m];
    float mxv = g_rowmax[m];
    float scopy = (1.f - p) / g_zc[m];

    const float4* L4 = (const float4*)(g_logits + base + head);
    float4* O4 = (float4*)(out + base + head);
    for (int i = blockIdx.x * 256 + threadIdx.x; i < nv4; i += gridDim.x * 256) {
        float4 v = L4[i];
        v.x = __logf(fmaf(sgen, __expf(v.x - mxv), scopy));
        v.y = __logf(fmaf(sgen, __expf(v.y - mxv), scopy));
        v.z = __logf(fmaf(sgen, __expf(v.z - mxv), scopy));
        v.w = __logf(fmaf(sgen, __expf(v.w - mxv), scopy));
        O4[i] = v;
    }
    if (blockIdx.x == 0 && threadIdx.x < (unsigned)(head + tail)) {
        int v = (threadIdx.x < (unsigned)head) ? (int)threadIdx.x
                                               : head + nv4 * 4 + ((int)threadIdx.x - head);
        float gl = g_logits[base + v];
        out[base + v] = __logf(fmaf(sgen, __expf(gl - mxv), scopy));
    }
}

// ======================= sparse copy fixup =======================
__global__ void k_fix(const int* __restrict__ src, float* __restrict__ out) {
    int m = blockIdx.x;
    int b = m % kB;
    int s = threadIdx.x;
    if (g_gid[b * kS + s] != s) return;   // leaders only
    int vv = src[(size_t)s * kB + b];
    float c = g_csum[(size_t)m * kS + s];
    float p = g_prob[m];
    float sgen = p / g_rowsum[m];
    float mxv = g_rowmax[m];
    float scopy = (1.f - p) / g_zc[m];
    float gl = g_logits[(size_t)m * kV + vv];
    out[(size_t)m * kV + vv] = __logf(fmaf(sgen, __expf(gl - mxv), scopy * __expf(c)));
}

extern "C" void kernel_launch(void* const* d_in, const int* in_sizes, int n_in,
                              void* d_out, int out_size) {
    const int*   src  = (const int*)d_in[0];    // src_full [S,B] int32
    const float* dec  = (const float*)d_in[1];  // decode_output [T,B,H]
    const float* attn = (const float*)d_in[2];  // decode_attn [B,T,S]
    const float* mem  = (const float*)d_in[3];  // memory [S,B,H]
    const float* Wg   = (const float*)d_in[4];  // W_gen [H,V]
    const float* bg   = (const float*)d_in[5];  // b_gen [V]
    const float* Wp   = (const float*)d_in[6];  // W_prob [H]
    const float* bp   = (const float*)d_in[7];  // b_prob [1]
    float* out = (float*)d_out;                 // [T,B,V] f32

    cudaFuncSetAttribute(k_gemm, cudaFuncAttributeMaxDynamicSharedMemorySize, GEMM_SMEM);

    k_at<<<(kH * kM / 2) / 256, 256>>>(dec);
    k_bpad2<<<dim3(NYB, 16), 256>>>(Wg);
    k_leader<<<kB, kS>>>(src);
    k_q<<<(kS * kB) / 4, 128>>>(mem, Wp);
    k_zc<<<kM, kS>>>(attn, bp);
    k_gemm<<<dim3(kM / BM, NYB), 256, GEMM_SMEM>>>(bg);
    k_rowfin<<<kM, 32>>>();
    k_logmix<<<dim3(13, kM), 256>>>(out);
    k_fix<<<kM, kS>>>(src, out);
}